// round 17
// baseline (speedup 1.0000x reference)
#include <cuda_runtime.h>
#include <cuda_bf16.h>

#define NUM_CLASSES 1000
#define FEAT_DIM    512
#define BATCH       65536
#define NBLK        16      // count-kernel blocks / partial histograms
#define GRID_D      2048    // dist blocks
#define SPW         4       // samples per warp (2048 blocks * 8 warps * 4 = 65536)

// Scratch. g_part/g_inv fully overwritten each call; g_ticket reset by the
// last count block (R6-proven pattern). The threadfence lives ONLY in the
// 16-block count kernel — dist stays fence-free (fences flush L1D: measured).
__device__ int      g_part[NUM_CLASSES * NBLK];
__device__ float    g_inv[NUM_CLASSES];
__device__ unsigned g_ticket;

// Launch 1: per-block smem histogram -> plain-store partials; LAST block folds
// partials into the per-class inverse weight table (4 KB) and resets ticket.
__global__ __launch_bounds__(1024) void count_kernel(
    const long long* __restrict__ labels, float* __restrict__ out)
{
    __shared__ int h[NUM_CLASSES];
    for (int j = threadIdx.x; j < NUM_CLASSES; j += 1024)
        h[j] = 0;
    if (blockIdx.x == 0 && threadIdx.x == 0)
        out[0] = 0.0f;
    __syncthreads();

    const int base = blockIdx.x * (BATCH / NBLK);
#pragma unroll
    for (int k = 0; k < BATCH / NBLK / 1024; k++) {
        int l = (int)labels[base + k * 1024 + threadIdx.x];
        atomicAdd_block(&h[l], 1);
    }
    __syncthreads();

    for (int j = threadIdx.x; j < NUM_CLASSES; j += 1024)
        g_part[j * NBLK + blockIdx.x] = h[j];

    // ---- last-block fold (fence cost: 16 blocks, cold caches — negligible) ----
    __shared__ bool s_last;
    if (threadIdx.x == 0) {
        __threadfence();
        unsigned t = atomicAdd(&g_ticket, 1);
        s_last = (t == NBLK - 1);
    }
    __syncthreads();
    if (!s_last) return;

    for (int j = threadIdx.x; j < NUM_CLASSES; j += 1024) {
        int c = 0;
#pragma unroll
        for (int b = 0; b < NBLK; b++)
            c += g_part[j * NBLK + b];
        g_inv[j] = (c > 0)
            ? 1.0f / ((float)c * ((float)FEAT_DIM * (float)BATCH))
            : 0.0f;
    }
    if (threadIdx.x == 0)
        g_ticket = 0;
}

// Launch 2: persistent warps, SPW samples each. R11-proven loop body
// (compiler-scheduled loads, no reg cap, no manual front-batch). Per-lane
// weighted accumulation — zero shuffles/smem/atomics inside the loop.
__global__ __launch_bounds__(256) void dist_kernel(
    const float4* __restrict__ feat,
    const float4* __restrict__ cent,
    const long long* __restrict__ labels,
    float* __restrict__ out)
{
    const int lane = threadIdx.x & 31;
    const int wid  = threadIdx.x >> 5;
    const int wg   = blockIdx.x * 8 + wid;     // 0..16383

    float vacc = 0.0f;

#pragma unroll 2
    for (int k = 0; k < SPW; k++) {
        const int sample = wg + k * (GRID_D * 8);
        const int lbl = (int)labels[sample];             // broadcast

        const float4* fr = feat + (size_t)sample * (FEAT_DIM / 4);
        const float4* cr = cent + (size_t)lbl    * (FEAT_DIM / 4);
        const float w = g_inv[lbl];                      // L1-hot 4 KB table

        float acc = 0.0f;
#pragma unroll
        for (int q = 0; q < 4; q++) {
            float4 a = fr[lane + 32 * q];
            float4 b = cr[lane + 32 * q];
            float dx = a.x - b.x;
            float dy = a.y - b.y;
            float dz = a.z - b.z;
            float dw = a.w - b.w;
            acc = fmaf(dx, dx, acc);
            acc = fmaf(dy, dy, acc);
            acc = fmaf(dz, dz, acc);
            acc = fmaf(dw, dw, acc);
        }

        vacc = fmaf(acc, w, vacc);    // w uniform per sample -> exact
    }

    // one warp reduce at the end
#pragma unroll
    for (int off = 16; off > 0; off >>= 1)
        vacc += __shfl_xor_sync(0xFFFFFFFFu, vacc, off);

    __shared__ float s[8];
    if (lane == 0) s[wid] = vacc;
    __syncthreads();

    if (threadIdx.x == 0) {
        float t = 0.0f;
#pragma unroll
        for (int w2 = 0; w2 < 8; w2++) t += s[w2];
        atomicAdd(out, t);            // single address, 2048 total
    }
}

extern "C" void kernel_launch(void* const* d_in, const int* in_sizes, int n_in,
                              void* d_out, int out_size) {
    const float4*    feat   = (const float4*)d_in[0];
    const float4*    cent   = (const float4*)d_in[1];
    const long long* labels = (const long long*)d_in[2];
    float* out = (float*)d_out;

    count_kernel<<<NBLK, 1024>>>(labels, out);
    dist_kernel<<<GRID_D, 256>>>(feat, cent, labels, out);
}